// round 5
// baseline (speedup 1.0000x reference)
#include <cuda_runtime.h>
#include <cstdint>
#include <math.h>

// ---------------------------------------------------------------------------
// AttentionHead: x[B,T,Dm] -> q,k,v = x@W+b -> causal softmax(q k^T * d^-0.5) @ v
// B=4, T=4096, Dm=1024, Dh=64, fp32 I/O.
// TF32 mma.sync. qkv writes TF32-pre-rounded q/k/v so flash can cp.async
// K/V tiles bit-identically with a double-buffered async pipeline.
// Flash: flat chunked KV-split (<=8 chunks of 512 KV rows) + combine pass.
// ---------------------------------------------------------------------------

#define FULLMASK 0xffffffffu

constexpr int BB = 4;
constexpr int TT = 4096;
constexpr int DM = 1024;
constexpr int DH = 64;
constexpr float QSCALE = 0.18033688011112042f;  // d^-0.5 * log2(e)

// q pre-scaled by QSCALE; all three pre-rounded to tf32
__device__ float g_q[BB * TT * DH];
__device__ float g_k[BB * TT * DH];
__device__ float g_v[BB * TT * DH];

constexpr int MAXS = 8;
__device__ float g_po[MAXS][BB * TT * DH];
__device__ float g_pm[MAXS][BB * TT];
__device__ float g_pl[MAXS][BB * TT];

// ------------------------------ helpers ------------------------------------

__device__ __forceinline__ uint32_t f2tf(float x) {
    uint32_t u;
    asm("cvt.rna.tf32.f32 %0, %1;" : "=r"(u) : "f"(x));
    return u;
}

__device__ __forceinline__ float ex2(float x) {
    float r;
    asm("ex2.approx.f32 %0, %1;" : "=f"(r) : "f"(x));
    return r;
}

__device__ __forceinline__ void mma8(float* d, const uint32_t* a, uint32_t b0, uint32_t b1) {
    asm("mma.sync.aligned.m16n8k8.row.col.f32.tf32.tf32.f32 "
        "{%0,%1,%2,%3}, {%4,%5,%6,%7}, {%8,%9}, {%0,%1,%2,%3};"
        : "+f"(d[0]), "+f"(d[1]), "+f"(d[2]), "+f"(d[3])
        : "r"(a[0]), "r"(a[1]), "r"(a[2]), "r"(a[3]), "r"(b0), "r"(b1));
}

__device__ __forceinline__ float4 cvt4(float4 v) {
    float4 o;
    o.x = __uint_as_float(f2tf(v.x));
    o.y = __uint_as_float(f2tf(v.y));
    o.z = __uint_as_float(f2tf(v.z));
    o.w = __uint_as_float(f2tf(v.w));
    return o;
}

__device__ __forceinline__ void cpa16(float* dst, const float* src) {
    uint32_t d = (uint32_t)__cvta_generic_to_shared(dst);
    asm volatile("cp.async.cg.shared.global [%0], [%1], 16;" :: "r"(d), "l"(src));
}
#define CP_COMMIT()  asm volatile("cp.async.commit_group;")
#define CP_WAIT(N)   asm volatile("cp.async.wait_group %0;" :: "n"(N))

// --------------------------- QKV projection --------------------------------
// 256 threads (8 warps: 2 m-halves x 4 n-quarters). Block tile M=64, N=192,
// K-chunk 16. Warp tile M=32 (mt=2) x N=48 (nt=6) -> acc 48 regs.
// Ping-pong smem, one barrier per chunk, register prefetch.
// Epilogue stores tf32-rounded values (q pre-scaled by QSCALE).

constexpr int P_BM = 64;
constexpr int P_KT = 16;
constexpr int XS_STR = 20;
constexpr int WS_STR = 196;
constexpr int NKC = DM / P_KT;

__global__ __launch_bounds__(256, 3) void qkv_proj(
    const float* __restrict__ x,
    const float* __restrict__ Wq, const float* __restrict__ bq,
    const float* __restrict__ Wk, const float* __restrict__ bk,
    const float* __restrict__ Wv, const float* __restrict__ bv)
{
    __shared__ float xs[2][P_BM * XS_STR];   // 2 x 5.1 KB
    __shared__ float ws[2][P_KT * WS_STR];   // 2 x 12.5 KB

    const int tid = threadIdx.x;
    const int lane = tid & 31;
    const int wrp = tid >> 5;
    const int g = lane >> 2;
    const int t = lane & 3;
    const int m_off = (wrp >> 2) * 32;
    const int n_q = wrp & 3;            // quarter: cols [48*n_q, 48*n_q+48)
    const int row0 = blockIdx.x * P_BM;

    const int xr = tid >> 2, xc = (tid & 3) * 4;   // 256 float4 = full x tile
    int wr[3], wcc[3];
    const float* wsrc[3];
#pragma unroll
    for (int it = 0; it < 3; it++) {
        int idx = tid + it * 256;       // 768 float4 = full W tile
        wr[it] = idx / 48;
        int cpos = (idx % 48) * 4;
        wcc[it] = cpos;
        int m = cpos >> 6;
        wsrc[it] = (m == 0) ? Wq : ((m == 1) ? Wk : Wv);
    }

    float acc[2][6][4];
#pragma unroll
    for (int a = 0; a < 2; a++)
#pragma unroll
        for (int b = 0; b < 6; b++)
#pragma unroll
            for (int c = 0; c < 4; c++) acc[a][b][c] = 0.f;

    float4 px, pw[3];
    px = *reinterpret_cast<const float4*>(x + (size_t)(row0 + xr) * DM + xc);
#pragma unroll
    for (int it = 0; it < 3; it++)
        pw[it] = *reinterpret_cast<const float4*>(wsrc[it] + (size_t)wr[it] * DH + (wcc[it] & 63));

    *reinterpret_cast<float4*>(&xs[0][xr * XS_STR + xc]) = cvt4(px);
#pragma unroll
    for (int it = 0; it < 3; it++)
        *reinterpret_cast<float4*>(&ws[0][wr[it] * WS_STR + wcc[it]]) = cvt4(pw[it]);
    __syncthreads();

    int cur = 0;
    for (int kc = 0; kc < NKC; kc++) {
        if (kc + 1 < NKC) {
            int k0n = (kc + 1) * P_KT;
            px = *reinterpret_cast<const float4*>(x + (size_t)(row0 + xr) * DM + k0n + xc);
#pragma unroll
            for (int it = 0; it < 3; it++)
                pw[it] = *reinterpret_cast<const float4*>(
                    wsrc[it] + (size_t)(k0n + wr[it]) * DH + (wcc[it] & 63));
        }

        const float* xb = xs[cur];
        const float* wb = ws[cur];
#pragma unroll
        for (int ks = 0; ks < 2; ks++) {
            uint32_t af[2][4];
#pragma unroll
            for (int mt = 0; mt < 2; mt++) {
                int rb = m_off + mt * 16;
                af[mt][0] = __float_as_uint(xb[(rb + g) * XS_STR + ks * 8 + t]);
                af[mt][1] = __float_as_uint(xb[(rb + g + 8) * XS_STR + ks * 8 + t]);
                af[mt][2] = __float_as_uint(xb[(rb + g) * XS_STR + ks * 8 + t + 4]);
                af[mt][3] = __float_as_uint(xb[(rb + g + 8) * XS_STR + ks * 8 + t + 4]);
            }
#pragma unroll
            for (int nt = 0; nt < 6; nt++) {
                int ncol = n_q * 48 + nt * 8 + g;
                uint32_t b0 = __float_as_uint(wb[(ks * 8 + t) * WS_STR + ncol]);
                uint32_t b1 = __float_as_uint(wb[(ks * 8 + t + 4) * WS_STR + ncol]);
#pragma unroll
                for (int mt = 0; mt < 2; mt++) mma8(acc[mt][nt], af[mt], b0, b1);
            }
        }

        if (kc + 1 < NKC) {
            int nxt = cur ^ 1;
            *reinterpret_cast<float4*>(&xs[nxt][xr * XS_STR + xc]) = cvt4(px);
#pragma unroll
            for (int it = 0; it < 3; it++)
                *reinterpret_cast<float4*>(&ws[nxt][wr[it] * WS_STR + wcc[it]]) = cvt4(pw[it]);
        }
        __syncthreads();
        cur ^= 1;
    }

    // epilogue: bias + scale + tf32 round + store
#pragma unroll
    for (int nt = 0; nt < 6; nt++) {
        int cg = n_q * 48 + nt * 8;          // global col group (8-aligned)
        int mi = cg >> 6;                    // 0=q 1=k 2=v (groups never straddle)
        int cin = (cg & 63) + 2 * t;
        const float* bias = (mi == 0) ? bq : ((mi == 1) ? bk : bv);
        float* outp = (mi == 0) ? g_q : ((mi == 1) ? g_k : g_v);
        const float qs = (mi == 0) ? QSCALE : 1.0f;
        float b0v = bias[cin], b1v = bias[cin + 1];
#pragma unroll
        for (int mt = 0; mt < 2; mt++) {
            int row = row0 + m_off + mt * 16 + g;
            float2 v0 = make_float2(
                __uint_as_float(f2tf((acc[mt][nt][0] + b0v) * qs)),
                __uint_as_float(f2tf((acc[mt][nt][1] + b1v) * qs)));
            float2 v1 = make_float2(
                __uint_as_float(f2tf((acc[mt][nt][2] + b0v) * qs)),
                __uint_as_float(f2tf((acc[mt][nt][3] + b1v) * qs)));
            *reinterpret_cast<float2*>(outp + (size_t)row * DH + cin) = v0;
            *reinterpret_cast<float2*>(outp + (size_t)(row + 8) * DH + cin) = v1;
        }
    }
}

// --------------------------- flash attention -------------------------------
// 128 threads, BM=64 Q rows, BN=32 KV sub-tile, double-buffered cp.async
// staging (K/V pre-rounded to tf32 in gmem -> bit-identical copy).
// Work unit = (batch, q-tile qi, chunk c): KV rows [512c, min(512c+512, 64qi+64)).
// Q fragments live in registers (pre-rounded, pre-scaled).

constexpr int A_BM = 64;
constexpr int A_BN = 32;
constexpr int A_C = 8;                    // 64-row units per chunk (=16 BN tiles)
constexpr int A_NCH = 288;                // sum_{qi<64} ceil((qi+1)/8)
constexpr int A_STR = 68;
constexpr int A_TSZ = A_BN * A_STR;       // 2176 floats

__global__ __launch_bounds__(128, 4) void flash_attn_split()
{
    __shared__ float Ks[2][A_TSZ];
    __shared__ float Vs[2][A_TSZ];

    const int b = blockIdx.y;
    const int flat = A_NCH - 1 - blockIdx.x;   // descending qi
    int qi = 0, base = 0;
    for (;;) {
        int nc = (qi + A_C) >> 3;
        if (flat < base + nc) break;
        base += nc;
        qi++;
    }
    const int c = flat - base;                 // chunk index < 8
    const int kbeg = c * 16;                           // in BN=32 tiles
    const int kend = min(kbeg + 16, 2 * qi + 2);

    const int row0 = qi * A_BM;
    const int tid = threadIdx.x;
    const int lane = tid & 31;
    const int w = tid >> 5;
    const int g = lane >> 2;
    const int t = lane & 3;

    const float* qb = g_q + (size_t)b * TT * DH;
    const float* kb = g_k + (size_t)b * TT * DH;
    const float* vb = g_v + (size_t)b * TT * DH;

    // Q fragments from gmem (already tf32-rounded + scaled)
    uint32_t qf[8][4];
    {
        int rA = row0 + w * 16 + g;
#pragma unroll
        for (int ks = 0; ks < 8; ks++) {
            qf[ks][0] = __float_as_uint(__ldg(qb + (size_t)rA * DH + ks * 8 + t));
            qf[ks][1] = __float_as_uint(__ldg(qb + (size_t)(rA + 8) * DH + ks * 8 + t));
            qf[ks][2] = __float_as_uint(__ldg(qb + (size_t)rA * DH + ks * 8 + t + 4));
            qf[ks][3] = __float_as_uint(__ldg(qb + (size_t)(rA + 8) * DH + ks * 8 + t + 4));
        }
    }

    // async stage of KV tile jj into buffer bf
    auto stage = [&](int jj, int bf) {
#pragma unroll
        for (int p = 0; p < 4; p++) {
            int f = tid + p * 128;
            int r = f >> 4, c4 = (f & 15) * 4;
            cpa16(&Ks[bf][r * A_STR + c4], kb + (size_t)(jj * A_BN + r) * DH + c4);
            cpa16(&Vs[bf][r * A_STR + c4], vb + (size_t)(jj * A_BN + r) * DH + c4);
        }
        CP_COMMIT();
    };

    float o[8][4];
#pragma unroll
    for (int nt = 0; nt < 8; nt++)
#pragma unroll
        for (int cc = 0; cc < 4; cc++) o[nt][cc] = 0.f;

    float mA = -INFINITY, mB = -INFINITY;
    float lA = 0.f, lB = 0.f;
    const int rAq = w * 16 + g;

    stage(kbeg, kbeg & 1);

    for (int jj = kbeg; jj < kend; jj++) {
        const int buf = jj & 1;
        if (jj + 1 < kend) {
            stage(jj + 1, buf ^ 1);
            CP_WAIT(1);
        } else {
            CP_WAIT(0);
        }
        __syncthreads();

        const float* Kb = Ks[buf];
        const float* Vb = Vs[buf];

        // S = Q K^T (scale*log2e folded into Q)
        float s[4][4];
#pragma unroll
        for (int nt = 0; nt < 4; nt++)
#pragma unroll
            for (int cc = 0; cc < 4; cc++) s[nt][cc] = 0.f;

#pragma unroll
        for (int ks = 0; ks < 8; ks++) {
#pragma unroll
            for (int nt = 0; nt < 4; nt++) {
                uint32_t b0 = __float_as_uint(Kb[(nt * 8 + g) * A_STR + ks * 8 + t]);
                uint32_t b1 = __float_as_uint(Kb[(nt * 8 + g) * A_STR + ks * 8 + t + 4]);
                mma8(s[nt], qf[ks], b0, b1);
            }
        }

        if (jj >= 2 * qi) {   // diagonal region: causal mask
            int rA = 64 * qi + rAq - 32 * jj;   // row minus tile col origin
            int rB = rA + 8;
#pragma unroll
            for (int nt = 0; nt < 4; nt++) {
                int c0 = nt * 8 + 2 * t, c1 = c0 + 1;
                if (c0 > rA) s[nt][0] = -INFINITY;
                if (c1 > rA) s[nt][1] = -INFINITY;
                if (c0 > rB) s[nt][2] = -INFINITY;
                if (c1 > rB) s[nt][3] = -INFINITY;
            }
        }

        // online softmax (base-2)
        float tmA = -INFINITY, tmB = -INFINITY;
#pragma unroll
        for (int nt = 0; nt < 4; nt++) {
            tmA = fmaxf(tmA, fmaxf(s[nt][0], s[nt][1]));
            tmB = fmaxf(tmB, fmaxf(s[nt][2], s[nt][3]));
        }
        tmA = fmaxf(tmA, __shfl_xor_sync(FULLMASK, tmA, 1));
        tmA = fmaxf(tmA, __shfl_xor_sync(FULLMASK, tmA, 2));
        tmB = fmaxf(tmB, __shfl_xor_sync(FULLMASK, tmB, 1));
        tmB = fmaxf(tmB, __shfl_xor_sync(FULLMASK, tmB, 2));
        float mAn = fmaxf(mA, tmA);
        float mBn = fmaxf(mB, tmB);
        float aA = ex2(mA - mAn);
        float aB = ex2(mB - mBn);
        mA = mAn; mB = mBn;

        float rsA = 0.f, rsB = 0.f;
#pragma unroll
        for (int nt = 0; nt < 4; nt++) {
            s[nt][0] = ex2(s[nt][0] - mAn); rsA += s[nt][0];
            s[nt][1] = ex2(s[nt][1] - mAn); rsA += s[nt][1];
            s[nt][2] = ex2(s[nt][2] - mBn); rsB += s[nt][2];
            s[nt][3] = ex2(s[nt][3] - mBn); rsB += s[nt][3];
        }
        lA = lA * aA + rsA;
        lB = lB * aB + rsB;
#pragma unroll
        for (int nt = 0; nt < 8; nt++) {
            o[nt][0] *= aA; o[nt][1] *= aA;
            o[nt][2] *= aB; o[nt][3] *= aB;
        }

        // O += P V : remap P C-frag -> A-frag via shuffles
        const int bse = lane & ~3;
        const int srcLo = bse + (t >> 1);
        const int srcHi = bse + 2 + (t >> 1);
        const bool odd = (t & 1);
#pragma unroll
        for (int kt = 0; kt < 4; kt++) {
            float u00 = __shfl_sync(FULLMASK, s[kt][0], srcLo);
            float u01 = __shfl_sync(FULLMASK, s[kt][1], srcLo);
            float u10 = __shfl_sync(FULLMASK, s[kt][0], srcHi);
            float u11 = __shfl_sync(FULLMASK, s[kt][1], srcHi);
            float w00 = __shfl_sync(FULLMASK, s[kt][2], srcLo);
            float w01 = __shfl_sync(FULLMASK, s[kt][3], srcLo);
            float w10 = __shfl_sync(FULLMASK, s[kt][2], srcHi);
            float w11 = __shfl_sync(FULLMASK, s[kt][3], srcHi);
            uint32_t pa[4];
            pa[0] = f2tf(odd ? u01 : u00);
            pa[1] = f2tf(odd ? w01 : w00);
            pa[2] = f2tf(odd ? u11 : u10);
            pa[3] = f2tf(odd ? w11 : w10);
#pragma unroll
            for (int nt = 0; nt < 8; nt++) {
                uint32_t b0 = __float_as_uint(Vb[(kt * 8 + t) * A_STR + nt * 8 + g]);
                uint32_t b1 = __float_as_uint(Vb[(kt * 8 + t + 4) * A_STR + nt * 8 + g]);
                mma8(o[nt], pa, b0, b1);
            }
        }
        __syncthreads();
    }

    // write unnormalized partials + m/l
    lA += __shfl_xor_sync(FULLMASK, lA, 1);
    lA += __shfl_xor_sync(FULLMASK, lA, 2);
    lB += __shfl_xor_sync(FULLMASK, lB, 1);
    lB += __shfl_xor_sync(FULLMASK, lB, 2);

    const size_t rbase = (size_t)b * TT + row0 + w * 16;
    float* po = g_po[c] + (rbase + g) * DH;
#pragma unroll
    for (int nt = 0; nt < 8; nt++) {
        int col = nt * 8 + 2 * t;
        *reinterpret_cast<float2*>(po + col) = make_float2(o[nt][0], o[nt][1]);
        *reinterpret_cast<float2*>(po + (size_t)8 * DH + col) = make_float2(o[nt][2], o[nt][3]);
    }
    if (t == 0) {
        g_pm[c][rbase + g] = mA;
        g_pm[c][rbase + g + 8] = mB;
        g_pl[c][rbase + g] = lA;
        g_pl[c][rbase + g + 8] = lB;
    }
}

// merge the per-chunk partials and normalize
__global__ __launch_bounds__(256) void combine(float* __restrict__ out)
{
    const int tid = threadIdx.x;
    const int row = blockIdx.x * 4 + (tid >> 6);      // global row in [0, B*T)
    const int col = tid & 63;

    const int qi = (row & (TT - 1)) >> 6;             // 64-row q-tile
    const int ns = (qi + A_C) >> 3;                   // number of chunks

    float mx = -INFINITY;
    for (int i = 0; i < ns; i++) mx = fmaxf(mx, g_pm[i][row]);

    const size_t idx = (size_t)row * DH + col;
    float den = 0.f, num = 0.f;
    for (int i = 0; i < ns; i++) {
        float f = ex2(g_pm[i][row] - mx);
        den += g_pl[i][row] * f;
        num += g_po[i][idx] * f;
    }
    out[idx] = num / den;
}

// ------------------------------- launch ------------------------------------

extern "C" void kernel_launch(void* const* d_in, const int* in_sizes, int n_in,
                              void* d_out, int out_size)
{
    const float* x  = (const float*)d_in[0];
    const float* Wq = (const float*)d_in[1];
    const float* bq = (const float*)d_in[2];
    const float* Wk = (const float*)d_in[3];
    const float* bk = (const float*)d_in[4];
    const float* Wv = (const float*)d_in[5];
    const float* bv = (const float*)d_in[6];
    float* out = (float*)d_out;

    qkv_proj<<<(BB * TT) / P_BM, 256>>>(x, Wq, bq, Wk, bk, Wv, bv);
    flash_attn_split<<<dim3(A_NCH, BB), 128>>>();
    combine<<<(BB * TT) / 4, 256>>>(out);
}

// round 7
// speedup vs baseline: 1.3526x; 1.3526x over previous
#include <cuda_runtime.h>
#include <cstdint>
#include <math.h>

// ---------------------------------------------------------------------------
// AttentionHead: x[B,T,Dm] -> q,k,v = x@W+b -> causal softmax(q k^T * d^-0.5) @ v
// B=4, T=4096, Dm=1024, Dh=64, fp32 I/O.
// TF32 mma.sync. qkv (R4 config) writes TF32-pre-rounded q/k/v so flash can
// cp.async K/V tiles bit-identically with a double-buffered async pipeline.
// Flash: flat chunked KV-split (<=8 chunks of 512 KV rows) + combine pass.
// ---------------------------------------------------------------------------

#define FULLMASK 0xffffffffu

constexpr int BB = 4;
constexpr int TT = 4096;
constexpr int DM = 1024;
constexpr int DH = 64;
constexpr float QSCALE = 0.18033688011112042f;  // d^-0.5 * log2(e)

// q pre-scaled by QSCALE; all three pre-rounded to tf32
__device__ float g_q[BB * TT * DH];
__device__ float g_k[BB * TT * DH];
__device__ float g_v[BB * TT * DH];

constexpr int MAXS = 8;
__device__ float g_po[MAXS][BB * TT * DH];
__device__ float g_pm[MAXS][BB * TT];
__device__ float g_pl[MAXS][BB * TT];

// ------------------------------ helpers ------------------------------------

__device__ __forceinline__ uint32_t f2tf(float x) {
    uint32_t u;
    asm("cvt.rna.tf32.f32 %0, %1;" : "=r"(u) : "f"(x));
    return u;
}

__device__ __forceinline__ float ex2(float x) {
    float r;
    asm("ex2.approx.f32 %0, %1;" : "=f"(r) : "f"(x));
    return r;
}

__device__ __forceinline__ void mma8(float* d, const uint32_t* a, uint32_t b0, uint32_t b1) {
    asm("mma.sync.aligned.m16n8k8.row.col.f32.tf32.tf32.f32 "
        "{%0,%1,%2,%3}, {%4,%5,%6,%7}, {%8,%9}, {%0,%1,%2,%3};"
        : "+f"(d[0]), "+f"(d[1]), "+f"(d[2]), "+f"(d[3])
        : "r"(a[0]), "r"(a[1]), "r"(a[2]), "r"(a[3]), "r"(b0), "r"(b1));
}

__device__ __forceinline__ float4 cvt4(float4 v) {
    float4 o;
    o.x = __uint_as_float(f2tf(v.x));
    o.y = __uint_as_float(f2tf(v.y));
    o.z = __uint_as_float(f2tf(v.z));
    o.w = __uint_as_float(f2tf(v.w));
    return o;
}

__device__ __forceinline__ void cpa16(float* dst, const float* src) {
    uint32_t d = (uint32_t)__cvta_generic_to_shared(dst);
    asm volatile("cp.async.cg.shared.global [%0], [%1], 16;" :: "r"(d), "l"(src));
}
#define CP_COMMIT()  asm volatile("cp.async.commit_group;")
#define CP_WAIT(N)   asm volatile("cp.async.wait_group %0;" :: "n"(N))

// --------------------------- QKV projection (R4 config) --------------------
// 192 threads (6 warps). Block tile: M=64 rows, N=192 cols (q|k|v), K-chunk 16.
// Warp w: matrix mi=w>>1, n-half=(w&1)*32. Warp tile M=64 x N=32 (mt=4,nt=4)
// -> 1.5 smem floats per mma. Ping-pong smem, ONE barrier per chunk,
// next chunk prefetched into registers under the mma block.
// Epilogue stores tf32-rounded values (q pre-scaled by QSCALE).

constexpr int P_BM = 64;
constexpr int P_KT = 16;
constexpr int XS_STR = 20;   // conflict-free A frags
constexpr int WS_STR = 196;  // conflict-free B frags
constexpr int NKC = DM / P_KT;

__global__ __launch_bounds__(192, 2) void qkv_proj(
    const float* __restrict__ x,
    const float* __restrict__ Wq, const float* __restrict__ bq,
    const float* __restrict__ Wk, const float* __restrict__ bk,
    const float* __restrict__ Wv, const float* __restrict__ bv)
{
    __shared__ float xs[2][P_BM * XS_STR];   // 2 x 5.1 KB
    __shared__ float ws[2][P_KT * WS_STR];   // 2 x 12.5 KB

    const int tid = threadIdx.x;
    const int lane = tid & 31;
    const int wrp = tid >> 5;
    const int g = lane >> 2;
    const int t = lane & 3;
    const int mi = wrp >> 1;            // 0=q 1=k 2=v
    const int n_loc = (wrp & 1) * 32;
    const int ncol = mi * 64 + n_loc;
    const int row0 = blockIdx.x * P_BM;

    // staging index precompute
    const int xr0 = tid >> 2,           xc0 = (tid & 3) * 4;          // idx < 192
    const int xr1 = (tid + 192) >> 2,   xc1 = ((tid + 192) & 3) * 4;  // idx < 256
    const bool xv1 = (tid + 192) < 256;
    int wr[4], wcc[4];
    const float* wsrc[4];
#pragma unroll
    for (int it = 0; it < 4; it++) {
        int idx = tid + it * 192;
        wr[it] = idx / 48;
        int cpos = (idx % 48) * 4;
        wcc[it] = cpos;
        int m = cpos >> 6;
        wsrc[it] = (m == 0) ? Wq : ((m == 1) ? Wk : Wv);
    }

    float acc[4][4][4];
#pragma unroll
    for (int a = 0; a < 4; a++)
#pragma unroll
        for (int b = 0; b < 4; b++)
#pragma unroll
            for (int c = 0; c < 4; c++) acc[a][b][c] = 0.f;

    float4 px0, px1, pw[4];
    // preload + stage chunk 0 into buffer 0
    px0 = *reinterpret_cast<const float4*>(x + (size_t)(row0 + xr0) * DM + xc0);
    if (xv1) px1 = *reinterpret_cast<const float4*>(x + (size_t)(row0 + xr1) * DM + xc1);
#pragma unroll
    for (int it = 0; it < 4; it++)
        pw[it] = *reinterpret_cast<const float4*>(wsrc[it] + (size_t)wr[it] * DH + (wcc[it] & 63));

    *reinterpret_cast<float4*>(&xs[0][xr0 * XS_STR + xc0]) = cvt4(px0);
    if (xv1) *reinterpret_cast<float4*>(&xs[0][xr1 * XS_STR + xc1]) = cvt4(px1);
#pragma unroll
    for (int it = 0; it < 4; it++)
        *reinterpret_cast<float4*>(&ws[0][wr[it] * WS_STR + wcc[it]]) = cvt4(pw[it]);
    __syncthreads();

    int cur = 0;
    for (int kc = 0; kc < NKC; kc++) {
        // prefetch next chunk (latency hidden under the mma block)
        if (kc + 1 < NKC) {
            int k0n = (kc + 1) * P_KT;
            px0 = *reinterpret_cast<const float4*>(x + (size_t)(row0 + xr0) * DM + k0n + xc0);
            if (xv1)
                px1 = *reinterpret_cast<const float4*>(x + (size_t)(row0 + xr1) * DM + k0n + xc1);
#pragma unroll
            for (int it = 0; it < 4; it++)
                pw[it] = *reinterpret_cast<const float4*>(
                    wsrc[it] + (size_t)(k0n + wr[it]) * DH + (wcc[it] & 63));
        }

        const float* xb = xs[cur];
        const float* wb = ws[cur];
#pragma unroll
        for (int ks = 0; ks < 2; ks++) {
            uint32_t af[4][4];
#pragma unroll
            for (int mt = 0; mt < 4; mt++) {
                int rb = mt * 16;
                af[mt][0] = __float_as_uint(xb[(rb + g) * XS_STR + ks * 8 + t]);
                af[mt][1] = __float_as_uint(xb[(rb + g + 8) * XS_STR + ks * 8 + t]);
                af[mt][2] = __float_as_uint(xb[(rb + g) * XS_STR + ks * 8 + t + 4]);
                af[mt][3] = __float_as_uint(xb[(rb + g + 8) * XS_STR + ks * 8 + t + 4]);
            }
#pragma unroll
            for (int nt = 0; nt < 4; nt++) {
                uint32_t b0 = __float_as_uint(wb[(ks * 8 + t) * WS_STR + ncol + nt * 8 + g]);
                uint32_t b1 = __float_as_uint(wb[(ks * 8 + t + 4) * WS_STR + ncol + nt * 8 + g]);
#pragma unroll
                for (int mt = 0; mt < 4; mt++) mma8(acc[mt][nt], af[mt], b0, b1);
            }
        }

        // stage next chunk into the other buffer
        if (kc + 1 < NKC) {
            int nxt = cur ^ 1;
            *reinterpret_cast<float4*>(&xs[nxt][xr0 * XS_STR + xc0]) = cvt4(px0);
            if (xv1) *reinterpret_cast<float4*>(&xs[nxt][xr1 * XS_STR + xc1]) = cvt4(px1);
#pragma unroll
            for (int it = 0; it < 4; it++)
                *reinterpret_cast<float4*>(&ws[nxt][wr[it] * WS_STR + wcc[it]]) = cvt4(pw[it]);
        }
        __syncthreads();
        cur ^= 1;
    }

    // epilogue: bias + scale + tf32 round + store
    const float* bias = (mi == 0) ? bq : ((mi == 1) ? bk : bv);
    float* outp = (mi == 0) ? g_q : ((mi == 1) ? g_k : g_v);
    const float qs = (mi == 0) ? QSCALE : 1.0f;
#pragma unroll
    for (int nt = 0; nt < 4; nt++) {
        int col = n_loc + nt * 8 + 2 * t;
        float b0v = bias[col], b1v = bias[col + 1];
#pragma unroll
        for (int mt = 0; mt < 4; mt++) {
            int row = row0 + mt * 16 + g;
            float2 v0 = make_float2(
                __uint_as_float(f2tf((acc[mt][nt][0] + b0v) * qs)),
                __uint_as_float(f2tf((acc[mt][nt][1] + b1v) * qs)));
            float2 v1 = make_float2(
                __uint_as_float(f2tf((acc[mt][nt][2] + b0v) * qs)),
                __uint_as_float(f2tf((acc[mt][nt][3] + b1v) * qs)));
            *reinterpret_cast<float2*>(outp + (size_t)row * DH + col) = v0;
            *reinterpret_cast<float2*>(outp + (size_t)(row + 8) * DH + col) = v1;
        }
    }
}

// --------------------------- flash attention -------------------------------
// 128 threads, BM=64 Q rows, BN=32 KV sub-tile, double-buffered cp.async
// staging (K/V pre-rounded to tf32 in gmem -> bit-identical copy).
// Work unit = (batch, q-tile qi, chunk c): KV rows [512c, min(512c+512, 64qi+64)).
// Q fragments live in registers (pre-rounded, pre-scaled).

constexpr int A_BM = 64;
constexpr int A_BN = 32;
constexpr int A_C = 8;                    // 64-row units per chunk (=16 BN tiles)
constexpr int A_NCH = 288;                // sum_{qi<64} ceil((qi+1)/8)
constexpr int A_STR = 68;
constexpr int A_TSZ = A_BN * A_STR;       // 2176 floats

__global__ __launch_bounds__(128, 4) void flash_attn_split()
{
    __shared__ float Ks[2][A_TSZ];
    __shared__ float Vs[2][A_TSZ];

    const int b = blockIdx.y;
    const int flat = A_NCH - 1 - blockIdx.x;   // descending qi
    int qi = 0, base = 0;
    for (;;) {
        int nc = (qi + A_C) >> 3;
        if (flat < base + nc) break;
        base += nc;
        qi++;
    }
    const int c = flat - base;                 // chunk index < 8
    const int kbeg = c * 16;                   // in BN=32 tiles
    const int kend = min(kbeg + 16, 2 * qi + 2);

    const int row0 = qi * A_BM;
    const int tid = threadIdx.x;
    const int lane = tid & 31;
    const int w = tid >> 5;
    const int g = lane >> 2;
    const int t = lane & 3;

    const float* qb = g_q + (size_t)b * TT * DH;
    const float* kb = g_k + (size_t)b * TT * DH;
    const float* vb = g_v + (size_t)b * TT * DH;

    // Q fragments from gmem (already tf32-rounded + scaled)
    uint32_t qf[8][4];
    {
        int rA = row0 + w * 16 + g;
#pragma unroll
        for (int ks = 0; ks < 8; ks++) {
            qf[ks][0] = __float_as_uint(__ldg(qb + (size_t)rA * DH + ks * 8 + t));
            qf[ks][1] = __float_as_uint(__ldg(qb + (size_t)(rA + 8) * DH + ks * 8 + t));
            qf[ks][2] = __float_as_uint(__ldg(qb + (size_t)rA * DH + ks * 8 + t + 4));
            qf[ks][3] = __float_as_uint(__ldg(qb + (size_t)(rA + 8) * DH + ks * 8 + t + 4));
        }
    }

    // async stage of KV tile jj into buffer bf
    auto stage = [&](int jj, int bf) {
#pragma unroll
        for (int p = 0; p < 4; p++) {
            int f = tid + p * 128;
            int r = f >> 4, c4 = (f & 15) * 4;
            cpa16(&Ks[bf][r * A_STR + c4], kb + (size_t)(jj * A_BN + r) * DH + c4);
            cpa16(&Vs[bf][r * A_STR + c4], vb + (size_t)(jj * A_BN + r) * DH + c4);
        }
        CP_COMMIT();
    };

    float o[8][4];
#pragma unroll
    for (int nt = 0; nt < 8; nt++)
#pragma unroll
        for (int cc = 0; cc < 4; cc++) o[nt][cc] = 0.f;

    float mA = -INFINITY, mB = -INFINITY;
    float lA = 0.f, lB = 0.f;
    const int rAq = w * 16 + g;

    stage(kbeg, kbeg & 1);

    for (int jj = kbeg; jj < kend; jj++) {
        const int buf = jj & 1;
        if (jj + 1 < kend) {
            stage(jj + 1, buf ^ 1);
            CP_WAIT(1);
        } else {
            CP_WAIT(0);
        }
        __syncthreads();

        const float* Kb = Ks[buf];
        const float* Vb = Vs[buf];

        // S = Q K^T (scale*log2e folded into Q)
        float s[4][4];
#pragma unroll
        for (int nt = 0; nt < 4; nt++)
#pragma unroll
            for (int cc = 0; cc < 4; cc++) s[nt][cc] = 0.f;

#pragma unroll
        for (int ks = 0; ks < 8; ks++) {
#pragma unroll
            for (int nt = 0; nt < 4; nt++) {
                uint32_t b0 = __float_as_uint(Kb[(nt * 8 + g) * A_STR + ks * 8 + t]);
                uint32_t b1 = __float_as_uint(Kb[(nt * 8 + g) * A_STR + ks * 8 + t + 4]);
                mma8(s[nt], qf[ks], b0, b1);
            }
        }

        if (jj >= 2 * qi) {   // diagonal region: causal mask
            int rA = 64 * qi + rAq - 32 * jj;   // row minus tile col origin
            int rB = rA + 8;
#pragma unroll
            for (int nt = 0; nt < 4; nt++) {
                int c0 = nt * 8 + 2 * t, c1 = c0 + 1;
                if (c0 > rA) s[nt][0] = -INFINITY;
                if (c1 > rA) s[nt][1] = -INFINITY;
                if (c0 > rB) s[nt][2] = -INFINITY;
                if (c1 > rB) s[nt][3] = -INFINITY;
            }
        }

        // online softmax (base-2)
        float tmA = -INFINITY, tmB = -INFINITY;
#pragma unroll
        for (int nt = 0; nt < 4; nt++) {
            tmA = fmaxf(tmA, fmaxf(s[nt][0], s[nt][1]));
            tmB = fmaxf(tmB, fmaxf(s[nt][2], s[nt][3]));
        }
        tmA = fmaxf(tmA, __shfl_xor_sync(FULLMASK, tmA, 1));
        tmA = fmaxf(tmA, __shfl_xor_sync(FULLMASK, tmA, 2));
        tmB = fmaxf(tmB, __shfl_xor_sync(FULLMASK, tmB, 1));
        tmB = fmaxf(tmB, __shfl_xor_sync(FULLMASK, tmB, 2));
        float mAn = fmaxf(mA, tmA);
        float mBn = fmaxf(mB, tmB);
        float aA = ex2(mA - mAn);
        float aB = ex2(mB - mBn);
        mA = mAn; mB = mBn;

        float rsA = 0.f, rsB = 0.f;
#pragma unroll
        for (int nt = 0; nt < 4; nt++) {
            s[nt][0] = ex2(s[nt][0] - mAn); rsA += s[nt][0];
            s[nt][1] = ex2(s[nt][1] - mAn); rsA += s[nt][1];
            s[nt][2] = ex2(s[nt][2] - mBn); rsB += s[nt][2];
            s[nt][3] = ex2(s[nt][3] - mBn); rsB += s[nt][3];
        }
        lA = lA * aA + rsA;
        lB = lB * aB + rsB;
#pragma unroll
        for (int nt = 0; nt < 8; nt++) {
            o[nt][0] *= aA; o[nt][1] *= aA;
            o[nt][2] *= aB; o[nt][3] *= aB;
        }

        // O += P V : remap P C-frag -> A-frag via shuffles
        const int bse = lane & ~3;
        const int srcLo = bse + (t >> 1);
        const int srcHi = bse + 2 + (t >> 1);
        const bool odd = (t & 1);
#pragma unroll
        for (int kt = 0; kt < 4; kt++) {
            float u00 = __shfl_sync(FULLMASK, s[kt][0], srcLo);
            float u01 = __shfl_sync(FULLMASK, s[kt][1], srcLo);
            float u10 = __shfl_sync(FULLMASK, s[kt][0], srcHi);
            float u11 = __shfl_sync(FULLMASK, s[kt][1], srcHi);
            float w00 = __shfl_sync(FULLMASK, s[kt][2], srcLo);
            float w01 = __shfl_sync(FULLMASK, s[kt][3], srcLo);
            float w10 = __shfl_sync(FULLMASK, s[kt][2], srcHi);
            float w11 = __shfl_sync(FULLMASK, s[kt][3], srcHi);
            uint32_t pa[4];
            pa[0] = f2tf(odd ? u01 : u00);
            pa[1] = f2tf(odd ? w01 : w00);
            pa[2] = f2tf(odd ? u11 : u10);
            pa[3] = f2tf(odd ? w11 : w10);
#pragma unroll
            for (int nt = 0; nt < 8; nt++) {
                uint32_t b0 = __float_as_uint(Vb[(kt * 8 + t) * A_STR + nt * 8 + g]);
                uint32_t b1 = __float_as_uint(Vb[(kt * 8 + t + 4) * A_STR + nt * 8 + g]);
                mma8(o[nt], pa, b0, b1);
            }
        }
        __syncthreads();
    }

    // write unnormalized partials + m/l
    lA += __shfl_xor_sync(FULLMASK, lA, 1);
    lA += __shfl_xor_sync(FULLMASK, lA, 2);
    lB += __shfl_xor_sync(FULLMASK, lB, 1);
    lB += __shfl_xor_sync(FULLMASK, lB, 2);

    const size_t rbase = (size_t)b * TT + row0 + w * 16;
    float* po = g_po[c] + (rbase + g) * DH;
#pragma unroll
    for (int nt = 0; nt < 8; nt++) {
        int col = nt * 8 + 2 * t;
        *reinterpret_cast<float2*>(po + col) = make_float2(o[nt][0], o[nt][1]);
        *reinterpret_cast<float2*>(po + (size_t)8 * DH + col) = make_float2(o[nt][2], o[nt][3]);
    }
    if (t == 0) {
        g_pm[c][rbase + g] = mA;
        g_pm[c][rbase + g + 8] = mB;
        g_pl[c][rbase + g] = lA;
        g_pl[c][rbase + g + 8] = lB;
    }
}

// merge the per-chunk partials and normalize
__global__ __launch_bounds__(256) void combine(float* __restrict__ out)
{
    const int tid = threadIdx.x;
    const int row = blockIdx.x * 4 + (tid >> 6);      // global row in [0, B*T)
    const int col = tid & 63;

    const int qi = (row & (TT - 1)) >> 6;             // 64-row q-tile
    const int ns = (qi + A_C) >> 3;                   // number of chunks

    float mx = -INFINITY;
    for (int i = 0; i < ns; i++) mx = fmaxf(mx, g_pm[i][row]);

    const size_t idx = (size_t)row * DH + col;
    float den = 0.f, num = 0.f;
    for (int i = 0; i < ns; i++) {
        float f = ex2(g_pm[i][row] - mx);
        den += g_pl[i][row] * f;
        num += g_po[i][idx] * f;
    }
    out[idx] = num / den;
}

// ------------------------------- launch ------------------------------------

extern "C" void kernel_launch(void* const* d_in, const int* in_sizes, int n_in,
                              void* d_out, int out_size)
{
    const float* x  = (const float*)d_in[0];
    const float* Wq = (const float*)d_in[1];
    const float* bq = (const float*)d_in[2];
    const float* Wk = (const float*)d_in[3];
    const float* bk = (const float*)d_in[4];
    const float* Wv = (const float*)d_in[5];
    const float* bv = (const float*)d_in[6];
    float* out = (float*)d_out;

    qkv_proj<<<(BB * TT) / P_BM, 192>>>(x, Wq, bq, Wk, bk, Wv, bv);
    flash_attn_split<<<dim3(A_NCH, BB), 128>>>();
    combine<<<(BB * TT) / 4, 256>>>(out);
}